// round 12
// baseline (speedup 1.0000x reference)
#include <cuda_runtime.h>
#include <math.h>

#define B_     16
#define S_     512
#define FRAME_ 438
#define DM_    800
#define H_     8
#define DH_    100
#define FFNN_  1024
#define HID_   1024
#define POSE_  274
#define WIN_   100
#define KPAD_  1408   /* 274 + 1024 = 1298 padded to 11*128 */
#define OWP_   1920   /* 1024 + 800 = 1824 padded to 15*128 */
#define ROWS_  (B_*S_)
#define G4_    4096   /* 4*HID */
#define NBLK_  256    /* persistent decoder grid; co-resident (2/SM x 148 = 296) */

// ---------------- persistent scratch (device globals; no allocs) ----------------
__device__ float g_x   [ROWS_*DM_];
__device__ float g_q   [ROWS_*DM_];
__device__ float g_k   [ROWS_*DM_];
__device__ float g_v   [ROWS_*DM_];
__device__ float g_att [ROWS_*DM_];
__device__ float g_y   [ROWS_*DM_];
__device__ float g_x1  [ROWS_*DM_];
__device__ float g_ffn [ROWS_*FFNN_];
__device__ float g_enc [ROWS_*DM_];
__device__ float g_WcatT[G4_*KPAD_];
__device__ float g_outWT[POSE_*OWP_];
__device__ float g_hbuf [B_*HID_];
__device__ float g_cbuf [B_*HID_];
__device__ float g_xcat0[B_*KPAD_];
__device__ float g_xcat1[B_*KPAD_];

// ---------------- software grid barrier ------------------------------------------
__device__ unsigned g_bar_cnt = 0;
__device__ unsigned g_bar_gen = 0;

__device__ __forceinline__ void grid_bar()
{
    __syncthreads();
    if (threadIdx.x == 0) {
        __threadfence();                                   // release prior writes
        unsigned gen = *(volatile unsigned*)&g_bar_gen;
        if (atomicAdd(&g_bar_cnt, 1u) == NBLK_ - 1) {
            g_bar_cnt = 0;
            __threadfence();
            *(volatile unsigned*)&g_bar_gen = gen + 1;     // release
        } else {
            while (*(volatile unsigned*)&g_bar_gen == gen)
                __nanosleep(40);                           // gentle poll
        }
        __threadfence();                                   // acquire
    }
    __syncthreads();
}

// ---------------- generic tiled fp32 GEMM, C = A(MxK) @ B(KxN) + epilogue ------
// EPI: 0 none | 1 +bias[n]+postable[posidx[row]*N+n] | 2 +extra[row,n]
//      3 relu(+bias) | 4 +bias[n]+extra[row,n]
template<int EPI>
__global__ __launch_bounds__(256)
void gemm_tile(const float* __restrict__ A, const float* __restrict__ Bm,
               float* __restrict__ C, int M, int N, int K,
               const float* __restrict__ bias, const float* __restrict__ extra,
               const int* __restrict__ posidx)
{
    __shared__ float As[16][68];
    __shared__ float Bs[16][68];
    int tid = threadIdx.x;
    int tx = tid & 15, ty = tid >> 4;
    int rowBase = blockIdx.y * 64;
    int colBase = blockIdx.x * 64;

    float acc[4][4];
#pragma unroll
    for (int i = 0; i < 4; i++)
#pragma unroll
        for (int j = 0; j < 4; j++) acc[i][j] = 0.f;

    int am  = tid >> 2;            // 0..63 (row within tile)
    int akq = (tid & 3) << 2;      // 0,4,8,12 (k within tile)
    int bkk = tid >> 4;            // 0..15
    int bnq = (tid & 15) << 2;     // 0..60

    int ktiles = (K + 15) >> 4;
    for (int kt = 0; kt < ktiles; kt++) {
        int k0 = kt << 4;
#pragma unroll
        for (int j = 0; j < 4; j++) {
            int kk = akq + j;
            As[kk][am] = (k0 + kk < K) ? A[(size_t)(rowBase + am) * K + k0 + kk] : 0.f;
        }
#pragma unroll
        for (int j = 0; j < 4; j++) {
            int nn = bnq + j;
            Bs[bkk][nn] = (k0 + bkk < K && colBase + nn < N)
                          ? Bm[(size_t)(k0 + bkk) * N + colBase + nn] : 0.f;
        }
        __syncthreads();
#pragma unroll
        for (int kk = 0; kk < 16; kk++) {
            float4 a4 = *(const float4*)&As[kk][ty << 2];
            float4 b4 = *(const float4*)&Bs[kk][tx << 2];
            float av[4] = {a4.x, a4.y, a4.z, a4.w};
            float bv[4] = {b4.x, b4.y, b4.z, b4.w};
#pragma unroll
            for (int i = 0; i < 4; i++)
#pragma unroll
                for (int j = 0; j < 4; j++)
                    acc[i][j] += av[i] * bv[j];
        }
        __syncthreads();
    }

#pragma unroll
    for (int i = 0; i < 4; i++) {
        int row = rowBase + (ty << 2) + i;
#pragma unroll
        for (int j = 0; j < 4; j++) {
            int col = colBase + (tx << 2) + j;
            if (col < N) {
                float v = acc[i][j];
                if (EPI == 1) v += bias[col] + extra[(size_t)posidx[row] * N + col];
                else if (EPI == 2) v += extra[(size_t)row * N + col];
                else if (EPI == 3) { v += bias[col]; v = fmaxf(v, 0.f); }
                else if (EPI == 4) v += bias[col] + extra[(size_t)row * N + col];
                C[(size_t)row * N + col] = v;
            }
        }
    }
}

// ---------------- banded attention: one block per (query, head, batch) ---------
__global__ __launch_bounds__(128)
void attn_kernel(const float* __restrict__ q, const float* __restrict__ k,
                 const float* __restrict__ v, float* __restrict__ o)
{
    int i = blockIdx.x, h = blockIdx.y, b = blockIdx.z;
    int tid = threadIdx.x;
    __shared__ float qs[DH_];
    __shared__ float sc[2 * WIN_ + 1];
    __shared__ float red[128];

    int jlo = i - WIN_; if (jlo < 0) jlo = 0;
    int jhi = i + WIN_; if (jhi > S_ - 1) jhi = S_ - 1;
    int cnt = jhi - jlo + 1;

    const float* qrow = q + ((size_t)(b * S_ + i)) * DM_ + h * DH_;
    if (tid < DH_) qs[tid] = qrow[tid];
    __syncthreads();

    float lmax = -3.0e38f;
    for (int jj = tid; jj < cnt; jj += 128) {
        const float* krow = k + ((size_t)(b * S_ + jlo + jj)) * DM_ + h * DH_;
        float s = 0.f;
#pragma unroll
        for (int d = 0; d < DH_; d += 4) {
            float4 kv = *(const float4*)&krow[d];
            float4 qv = *(const float4*)&qs[d];
            s += qv.x * kv.x + qv.y * kv.y + qv.z * kv.z + qv.w * kv.w;
        }
        s = s / 10.0f;   // 1/sqrt(DH)
        sc[jj] = s;
        lmax = fmaxf(lmax, s);
    }
    red[tid] = lmax; __syncthreads();
    for (int st = 64; st > 0; st >>= 1) {
        if (tid < st) red[tid] = fmaxf(red[tid], red[tid + st]);
        __syncthreads();
    }
    float mx = red[0];
    __syncthreads();

    float lsum = 0.f;
    for (int jj = tid; jj < cnt; jj += 128) {
        float p = __expf(sc[jj] - mx);
        sc[jj] = p;
        lsum += p;
    }
    __syncthreads();           // all reads of red[0] done before rewrite
    red[tid] = lsum; __syncthreads();
    for (int st = 64; st > 0; st >>= 1) {
        if (tid < st) red[tid] += red[tid + st];
        __syncthreads();
    }
    float inv = 1.0f / red[0];

    if (tid < DH_) {
        float acc = 0.f;
        const float* vbase = v + ((size_t)(b * S_ + jlo)) * DM_ + h * DH_ + tid;
        for (int jj = 0; jj < cnt; jj++)
            acc += sc[jj] * vbase[(size_t)jj * DM_];
        o[((size_t)(b * S_ + i)) * DM_ + h * DH_ + tid] = acc * inv;
    }
}

// ---------------- LayerNorm over last dim (N=800) -------------------------------
__global__ __launch_bounds__(256)
void ln_rows(const float* __restrict__ in, float* __restrict__ out,
             const float* __restrict__ g, const float* __restrict__ bta, int N)
{
    int row = blockIdx.x, tid = threadIdx.x;
    __shared__ float red[256];
    const float* r = in + (size_t)row * N;

    float s = 0.f;
    for (int d = tid; d < N; d += 256) s += r[d];
    red[tid] = s; __syncthreads();
    for (int st = 128; st > 0; st >>= 1) { if (tid < st) red[tid] += red[tid + st]; __syncthreads(); }
    float mean = red[0] / (float)N;
    __syncthreads();

    float vs = 0.f;
    for (int d = tid; d < N; d += 256) { float df = r[d] - mean; vs += df * df; }
    __syncthreads();           // reads of red[0] done
    red[tid] = vs; __syncthreads();
    for (int st = 128; st > 0; st >>= 1) { if (tid < st) red[tid] += red[tid + st]; __syncthreads(); }
    float inv = rsqrtf(red[0] / (float)N + 1e-6f);

    float* w = out + (size_t)row * N;
    for (int d = tid; d < N; d += 256)
        w[d] = (r[d] - mean) * inv * g[d] + bta[d];
}

// ---------------- decoder setup kernels -----------------------------------------
// WcatT: row n (0..4095) holds K-vector for gate column n; gate g, hidden j is
// row (g*1024 + j). Stored [4096][KPAD].
__global__ void build_wcatT(const float* __restrict__ Wx, const float* __restrict__ Wh,
                            float* __restrict__ WT)
{
    int idx = blockIdx.x * blockDim.x + threadIdx.x;   // over KPAD_*G4_
    if (idx >= KPAD_ * G4_) return;
    int kk = idx / G4_, n = idx % G4_;                 // read coalesced over n
    float v = 0.f;
    if (kk < POSE_)                 v = Wx[(size_t)kk * G4_ + n];
    else if (kk < POSE_ + HID_)     v = Wh[(size_t)(kk - POSE_) * G4_ + n];
    WT[(size_t)n * KPAD_ + kk] = v;
}

__global__ void build_outWT(const float* __restrict__ outW, float* __restrict__ WT)
{
    int idx = blockIdx.x * blockDim.x + threadIdx.x;   // over OWP_*POSE_
    if (idx >= OWP_ * POSE_) return;
    int kk = idx / POSE_, p = idx % POSE_;
    float v = (kk < HID_ + DM_) ? outW[(size_t)kk * POSE_ + p] : 0.f;
    WT[(size_t)p * OWP_ + kk] = v;
}

__global__ void init_dec(const float* __restrict__ tgt, const float* __restrict__ dec0,
                         const float* __restrict__ vh, const float* __restrict__ vc,
                         const int* __restrict__ epoch,
                         float* __restrict__ x0, float* __restrict__ x1,
                         float* __restrict__ c)
{
    int idx = blockIdx.x * blockDim.x + threadIdx.x;   // over B_*KPAD_
    if (idx >= B_ * KPAD_) return;
    int b = idx / KPAD_, kk = idx % KPAD_;
    int ps = (int)((double)__ldg(epoch) * 0.01);
    bool m0 = (ps == 0);                               // pattern[0] is 1 iff p==0
    float v = 0.f;
    if (kk < POSE_)             v = m0 ? tgt[((size_t)(b * S_)) * POSE_ + kk] : dec0[b * POSE_ + kk];
    else if (kk < POSE_ + HID_) v = vh[b * HID_ + (kk - POSE_)];
    x0[idx] = v;
    x1[idx] = 0.f;                                     // pad region must be 0 in both
    if (kk < HID_) c[b * HID_ + kk] = vc[b * HID_ + kk];
}

// ---------------- persistent decoder: all 512 steps in ONE launch ---------------
__device__ __forceinline__ float sigm(float x) { return 1.0f / (1.0f + __expf(-x)); }

__global__ __launch_bounds__(256, 2)
void decoder_persistent(const float* __restrict__ WT, const float* __restrict__ oWT,
                        const float* __restrict__ lb, const float* __restrict__ ob,
                        const float* __restrict__ enc, const float* __restrict__ tgt,
                        const int* __restrict__ epoch,
                        float* __restrict__ c, float* __restrict__ h,
                        float* __restrict__ xb0, float* __restrict__ xb1,
                        float* __restrict__ dout)
{
    int tid  = threadIdx.x;
    int wid  = tid >> 5;
    int lane = tid & 31;
    int gw   = blockIdx.x * 8 + wid;                   // global warp 0..2047

    // phase A mapping: block owns 4 hidden indices; warp = (jslot, gpair)
    int jslot = wid >> 1;                              // 0..3
    int gpair = wid & 1;                               // 0:{i,f} 1:{g,o}
    int jA = blockIdx.x * 4 + jslot;                   // 0..1023
    const float* wA0 = WT + (size_t)((gpair * 2 + 0) * 1024 + jA) * KPAD_;
    const float* wA1 = WT + (size_t)((gpair * 2 + 1) * 1024 + jA) * KPAD_;

    // phase B mapping: warp gw handles output column gw (if < POSE_)
    const float* wrowB = oWT + (size_t)(gw < POSE_ ? gw : 0) * OWP_;

    int ps = (int)((double)__ldg(epoch) * 0.01);
    int period = ps + 10;

    __shared__ float st[4][4][16];

    for (int t = 0; t < S_; t++) {
        const float* xin  = (t & 1) ? xb1 : xb0;
        float*       xout = (t & 1) ? xb0 : xb1;

        // ---------- phase A: gates GEMM + cell ----------
        float acc0[16], acc1[16];
#pragma unroll
        for (int b = 0; b < 16; b++) { acc0[b] = 0.f; acc1[b] = 0.f; }

#pragma unroll 1
        for (int it = 0; it < KPAD_ / 128; it++) {
            int kk = (lane << 2) + (it << 7);
            float4 wa = __ldg((const float4*)(wA0 + kk));
            float4 wb = __ldg((const float4*)(wA1 + kk));
#pragma unroll
            for (int b = 0; b < 16; b++) {
                float4 xv = __ldg((const float4*)(xin + b * KPAD_ + kk));
                acc0[b] += xv.x * wa.x + xv.y * wa.y + xv.z * wa.z + xv.w * wa.w;
                acc1[b] += xv.x * wb.x + xv.y * wb.y + xv.z * wb.z + xv.w * wb.w;
            }
        }
#pragma unroll
        for (int b = 0; b < 16; b++)
#pragma unroll
            for (int off = 16; off > 0; off >>= 1) {
                acc0[b] += __shfl_xor_sync(0xffffffffu, acc0[b], off);
                acc1[b] += __shfl_xor_sync(0xffffffffu, acc1[b], off);
            }
        if (lane == 0) {
#pragma unroll
            for (int b = 0; b < 16; b++) {
                st[jslot][gpair * 2 + 0][b] = acc0[b];
                st[jslot][gpair * 2 + 1][b] = acc1[b];
            }
        }
        __syncthreads();

        if (tid < 64) {
            int js = tid >> 4;                 // 0..3
            int b  = tid & 15;                 // batch
            int jj = blockIdx.x * 4 + js;
            float ig = st[js][0][b] + __ldg(lb + jj);
            float fg = st[js][1][b] + __ldg(lb + 1024 + jj);
            float gg = st[js][2][b] + __ldg(lb + 2048 + jj);
            float og = st[js][3][b] + __ldg(lb + 3072 + jj);
            int ci = b * HID_ + jj;
            float cn = sigm(fg) * c[ci] + sigm(ig) * tanhf(gg);
            float hn = sigm(og) * tanhf(cn);
            c[ci] = cn;
            h[ci] = hn;
            xout[b * KPAD_ + POSE_ + jj] = hn;
        }
        grid_bar();

        // ---------- phase B: outproj + scheduled sampling ----------
        if (gw < POSE_) {
            float acc[16];
#pragma unroll
            for (int b = 0; b < 16; b++) acc[b] = 0.f;

#pragma unroll 1
            for (int it = 0; it < 8; it++) {           // h part, k in [0,1024)
                int kk = (lane << 2) + (it << 7);
                float4 w = __ldg((const float4*)(wrowB + kk));
#pragma unroll
                for (int b = 0; b < 16; b++) {
                    float4 xv = __ldg((const float4*)(h + b * HID_ + kk));
                    acc[b] += xv.x * w.x + xv.y * w.y + xv.z * w.z + xv.w * w.w;
                }
            }
#pragma unroll 1
            for (int it = 0; it < 7; it++) {           // enc part, k in [0,800)
                int kk = (lane << 2) + (it << 7);
                if (kk < DM_) {
                    float4 w = __ldg((const float4*)(wrowB + HID_ + kk));
#pragma unroll
                    for (int b = 0; b < 16; b++) {
                        float4 xv = __ldg((const float4*)(enc + ((size_t)(b * S_ + t)) * DM_ + kk));
                        acc[b] += xv.x * w.x + xv.y * w.y + xv.z * w.z + xv.w * w.w;
                    }
                }
            }
#pragma unroll
            for (int b = 0; b < 16; b++)
#pragma unroll
                for (int off = 16; off > 0; off >>= 1)
                    acc[b] += __shfl_xor_sync(0xffffffffu, acc[b], off);

            if (lane == 0) {
                bool use_tgt = (((t + 1) % period) >= ps);
                float bias = __ldg(ob + gw);
#pragma unroll
                for (int b = 0; b < 16; b++) {
                    float val = acc[b] + bias;
                    dout[((size_t)(b * S_ + t)) * POSE_ + gw] = val;
                    if (t + 1 < S_) {
                        float nx = use_tgt
                                 ? __ldg(tgt + ((size_t)(b * S_ + t + 1)) * POSE_ + gw)
                                 : val;
                        xout[b * KPAD_ + gw] = nx;
                    }
                }
            }
        }
        grid_bar();
    }
}

// ---------------- launcher -------------------------------------------------------
extern "C" void kernel_launch(void* const* d_in, const int* in_sizes, int n_in,
                              void* d_out, int out_size)
{
    const float* src_seq = (const float*)d_in[0];
    const int*   src_pos = (const int*)  d_in[1];
    const float* tgt_seq = (const float*)d_in[2];
    const float* vec_h   = (const float*)d_in[3];
    const float* vec_c   = (const float*)d_in[4];
    const float* dec0    = (const float*)d_in[5];
    const float* emb_W   = (const float*)d_in[6];
    const float* emb_b   = (const float*)d_in[7];
    const float* pos_tab = (const float*)d_in[8];
    const float* Wq      = (const float*)d_in[9];
    const float* Wk      = (const float*)d_in[10];
    const float* Wv      = (const float*)d_in[11];
    const float* Wo      = (const float*)d_in[12];
    const float* ln1_g   = (const float*)d_in[13];
    const float* ln1_b   = (const float*)d_in[14];
    const float* ffn_W1  = (const float*)d_in[15];
    const float* ffn_b1  = (const float*)d_in[16];
    const float* ffn_W2  = (const float*)d_in[17];
    const float* ffn_b2  = (const float*)d_in[18];
    const float* ln2_g   = (const float*)d_in[19];
    const float* ln2_b   = (const float*)d_in[20];
    const float* lstm_Wx = (const float*)d_in[21];
    const float* lstm_Wh = (const float*)d_in[22];
    const float* lstm_b  = (const float*)d_in[23];
    const float* out_W   = (const float*)d_in[24];
    const float* out_b   = (const float*)d_in[25];
    const int*   epoch   = (const int*)  d_in[26];
    float* dout = (float*)d_out;

    float *x, *q, *k, *v, *att, *y, *x1, *ffn, *enc;
    float *WcT, *oWT, *h, *c, *xc0, *xc1;
    cudaGetSymbolAddress((void**)&x,    g_x);
    cudaGetSymbolAddress((void**)&q,    g_q);
    cudaGetSymbolAddress((void**)&k,    g_k);
    cudaGetSymbolAddress((void**)&v,    g_v);
    cudaGetSymbolAddress((void**)&att,  g_att);
    cudaGetSymbolAddress((void**)&y,    g_y);
    cudaGetSymbolAddress((void**)&x1,   g_x1);
    cudaGetSymbolAddress((void**)&ffn,  g_ffn);
    cudaGetSymbolAddress((void**)&enc,  g_enc);
    cudaGetSymbolAddress((void**)&WcT,  g_WcatT);
    cudaGetSymbolAddress((void**)&oWT,  g_outWT);
    cudaGetSymbolAddress((void**)&h,    g_hbuf);
    cudaGetSymbolAddress((void**)&c,    g_cbuf);
    cudaGetSymbolAddress((void**)&xc0,  g_xcat0);
    cudaGetSymbolAddress((void**)&xc1,  g_xcat1);

    dim3 gEmb(13, ROWS_ / 64);   // N=800 -> 13 tiles
    dim3 gFfn(16, ROWS_ / 64);   // N=1024 -> 16 tiles

    // --------- encoder ---------
    gemm_tile<1><<<gEmb, 256>>>(src_seq, emb_W, x, ROWS_, DM_, FRAME_, emb_b, pos_tab, src_pos);
    gemm_tile<0><<<gEmb, 256>>>(x, Wq, q, ROWS_, DM_, DM_, nullptr, nullptr, nullptr);
    gemm_tile<0><<<gEmb, 256>>>(x, Wk, k, ROWS_, DM_, DM_, nullptr, nullptr, nullptr);
    gemm_tile<0><<<gEmb, 256>>>(x, Wv, v, ROWS_, DM_, DM_, nullptr, nullptr, nullptr);

    dim3 gAtt(S_, H_, B_);
    attn_kernel<<<gAtt, 128>>>(q, k, v, att);

    gemm_tile<2><<<gEmb, 256>>>(att, Wo, y, ROWS_, DM_, DM_, nullptr, x, nullptr);
    ln_rows<<<ROWS_, 256>>>(y, x1, ln1_g, ln1_b, DM_);
    gemm_tile<3><<<gFfn, 256>>>(x1, ffn_W1, ffn, ROWS_, FFNN_, DM_, ffn_b1, nullptr, nullptr);
    gemm_tile<4><<<gEmb, 256>>>(ffn, ffn_W2, y, ROWS_, DM_, FFNN_, ffn_b2, x1, nullptr);
    ln_rows<<<ROWS_, 256>>>(y, enc, ln2_g, ln2_b, DM_);

    // --------- decoder setup ---------
    build_wcatT<<<(KPAD_ * G4_ + 255) / 256, 256>>>(lstm_Wx, lstm_Wh, WcT);
    build_outWT<<<(OWP_ * POSE_ + 255) / 256, 256>>>(out_W, oWT);
    init_dec<<<(B_ * KPAD_ + 255) / 256, 256>>>(tgt_seq, dec0, vec_h, vec_c, epoch, xc0, xc1, c);

    // --------- decoder: ONE persistent kernel for all 512 steps ---------
    decoder_persistent<<<NBLK_, 256>>>(WcT, oWT, lstm_b, out_b, enc, tgt_seq, epoch,
                                       c, h, xc0, xc1, dout);
}